// round 4
// baseline (speedup 1.0000x reference)
#include <cuda_runtime.h>
#include <cstdint>
#include <cstddef>

#define BQ   16
#define HDIM 64
#define WDIM 64
#define CIN  256
#define COUT 256
#define NTAP 9

#define TH 16
#define TW 8
#define BK 16
#define XS_PS 20      /* floats per halo pixel: 16 ci + 4 pad (bank-conflict-free frag loads) */
#define BS_NS 136     /* floats per Bs k-row: 128 + 8 pad (conflict-free, 16B-aligned rows) */
#define HP (TH+2)
#define WP (TW+2)
#define NPIX (HP*WP)                 /* 180 halo pixels */
#define NSTAGE (NTAP*(CIN/BK))       /* 144 k-stages */

// Scratch (device globals; no runtime allocation)
__device__ float g_xmod[(size_t)BQ*HDIM*WDIM*CIN];   // modulated + tf32-rounded x (64 MB)
__device__ float g_wt[NTAP*CIN*COUT];                // tf32-rounded weights [k=tap*256+ci][co]
__device__ float g_demod[BQ*COUT];                   // per (b,co) demod scale

__device__ __forceinline__ float rna_tf32(float f) {
    uint32_t u;
    asm("cvt.rna.tf32.f32 %0, %1;" : "=r"(u) : "f"(f));
    return __uint_as_float(u);
}

// ---------------- prep kernels ----------------

__global__ void prep_w_kernel(const float* __restrict__ kern) {
    int i = blockIdx.x * blockDim.x + threadIdx.x;          // float4 index, exact grid
    float4 v = reinterpret_cast<const float4*>(kern)[i];
    v.x = rna_tf32(v.x); v.y = rna_tf32(v.y);
    v.z = rna_tf32(v.z); v.w = rna_tf32(v.w);
    reinterpret_cast<float4*>(g_wt)[i] = v;
}

__global__ void prep_demod_kernel(const float* __restrict__ kern,
                                  const float* __restrict__ style) {
    int b  = blockIdx.x;
    int co = threadIdx.x;
    float acc[NTAP];
    #pragma unroll
    for (int t = 0; t < NTAP; ++t) acc[t] = 0.0f;
    for (int ci = 0; ci < CIN; ++ci) {
        float s  = style[b*CIN + ci] + 1.0f;
        float s2 = s * s;
        #pragma unroll
        for (int t = 0; t < NTAP; ++t) {
            float v = kern[(t*CIN + ci)*COUT + co];
            acc[t] += v * v * s2;
        }
    }
    float a = ((acc[0]+acc[1])+(acc[2]+acc[3]))+((acc[4]+acc[5])+(acc[6]+acc[7]))+acc[8];
    g_demod[b*COUT + co] = rsqrtf(a + 1e-8f);
}

__global__ void prep_x_kernel(const float* __restrict__ x,
                              const float* __restrict__ style) {
    int i = blockIdx.x * blockDim.x + threadIdx.x;          // float4 index, exact grid
    int e = i << 2;
    int ci = e & (CIN - 1);
    int b  = e >> 20;                                       // 2^20 elems per sample
    float4 v = reinterpret_cast<const float4*>(x)[i];
    float4 s = reinterpret_cast<const float4*>(style)[(b*CIN + ci) >> 2];
    v.x = rna_tf32(v.x * (s.x + 1.0f));
    v.y = rna_tf32(v.y * (s.y + 1.0f));
    v.z = rna_tf32(v.z * (s.z + 1.0f));
    v.w = rna_tf32(v.w * (s.w + 1.0f));
    reinterpret_cast<float4*>(g_xmod)[i] = v;
}

// ---------------- main implicit-GEMM conv ----------------

__global__ void __launch_bounds__(256, 2) modconv_kernel(float* __restrict__ out) {
    __shared__ float xs[NPIX * XS_PS];        // 14400 B: halo tile [18][10][16ci] (+pad)
    __shared__ float bsm[2][BK * BS_NS];      // 17408 B: double-buffered B stage [16][128] (+pad)

    const int tid  = threadIdx.x;
    const int lane = tid & 31;
    const int wid  = tid >> 5;
    const int warp_m = wid >> 2;   // 0..1
    const int warp_n = wid & 3;    // 0..3
    const int gid = lane >> 2;
    const int tig = lane & 3;

    const int bt     = blockIdx.x;
    const int n_tile = bt & 1;
    const int mt     = bt >> 1;
    const int b      = mt >> 5;
    const int tI     = mt & 31;
    const int h0     = (tI >> 3) << 4;     // *16
    const int w0     = (tI & 7) << 3;      // *8
    const int co0    = n_tile << 7;        // *128

    // A-fragment pixel offsets (floats, already *XS_PS), halo origin (+1,+1)
    int pixo[8];
    #pragma unroll
    for (int mf = 0; mf < 4; ++mf) {
        #pragma unroll
        for (int hf = 0; hf < 2; ++hf) {
            int i  = warp_m*64 + mf*16 + hf*8 + gid;
            int hi = i >> 3, wi = i & 7;
            pixo[mf*2 + hf] = ((hi + 1)*WP + (wi + 1)) * XS_PS;
        }
    }

    const uint32_t xs_s   = (uint32_t)__cvta_generic_to_shared(xs);
    const uint32_t bs_s0  = (uint32_t)__cvta_generic_to_shared(bsm[0]);
    const uint32_t bs_s1  = (uint32_t)__cvta_generic_to_shared(bsm[1]);

    auto stage_x = [&](int chunk) {
        int ci0 = chunk * BK;
        #pragma unroll 1
        for (int t = tid; t < NPIX * (BK/4); t += 256) {      // 720 float4 tasks
            int pix = t >> 2;
            int c4  = t & 3;
            int hh  = pix / WP;
            int ww  = pix - hh * WP;
            int gh  = h0 - 1 + hh;
            int gw  = w0 - 1 + ww;
            bool ok = ((unsigned)gh < HDIM) && ((unsigned)gw < WDIM);
            const float* src = g_xmod;
            if (ok) src = g_xmod + ((size_t)((b*HDIM + gh)*WDIM + gw))*CIN + ci0 + c4*4;
            int sz = ok ? 16 : 0;
            uint32_t dst = xs_s + (uint32_t)(pix*XS_PS + c4*4) * 4u;
            asm volatile("cp.async.cg.shared.global [%0], [%1], 16, %2;\n"
                         :: "r"(dst), "l"(src), "r"(sz));
        }
    };

    auto stage_b = [&](int s) {
        int tap   = s % NTAP;
        int chunk = s / NTAP;
        int krow  = tap*CIN + chunk*BK;
        uint32_t base = (s & 1) ? bs_s1 : bs_s0;
        #pragma unroll 1
        for (int t = tid; t < BK * 32; t += 256) {            // 512 float4 tasks
            int kr = t >> 5;
            int n4 = t & 31;
            const float* src = g_wt + (size_t)(krow + kr)*COUT + co0 + n4*4;
            uint32_t dst = base + (uint32_t)(kr*BS_NS + n4*4) * 4u;
            asm volatile("cp.async.cg.shared.global [%0], [%1], 16;\n"
                         :: "r"(dst), "l"(src));
        }
    };

    float acc[4][4][4];
    #pragma unroll
    for (int mf = 0; mf < 4; ++mf)
        #pragma unroll
        for (int nf = 0; nf < 4; ++nf)
            #pragma unroll
            for (int r = 0; r < 4; ++r) acc[mf][nf][r] = 0.0f;

    // Prologue: first x chunk + first B stage
    stage_x(0);
    asm volatile("cp.async.commit_group;\n");
    stage_b(0);
    asm volatile("cp.async.commit_group;\n");

    for (int s = 0; s < NSTAGE; ++s) {
        __syncthreads();   // all warps done with previous stage's smem (xs + both B buffers safe)

        if (s > 0 && (s % NTAP) == 0) {       // new ci-chunk: reload halo tile (single buffer)
            stage_x(s / NTAP);
            asm volatile("cp.async.commit_group;\n");
        }
        if (s + 1 < NSTAGE) {                 // prefetch next B stage into other buffer
            stage_b(s + 1);
            asm volatile("cp.async.commit_group;\n");
            asm volatile("cp.async.wait_group 1;\n");   // everything except newest prefetch done
        } else {
            asm volatile("cp.async.wait_group 0;\n");
        }
        __syncthreads();

        const int tap = s % NTAP;
        const float* bsp = bsm[s & 1];
        const int toff = ((tap/3)*WP + (tap%3) - (WP + 1)) * XS_PS;   // (dh*WP+dw)*XS_PS

        #pragma unroll
        for (int kk = 0; kk < BK; kk += 8) {
            uint32_t afr[4][4], bfr[4][2];
            #pragma unroll
            for (int mf = 0; mf < 4; ++mf) {
                const float* p0 = xs + pixo[mf*2 + 0] + toff + kk + tig;
                const float* p1 = xs + pixo[mf*2 + 1] + toff + kk + tig;
                afr[mf][0] = __float_as_uint(p0[0]);
                afr[mf][1] = __float_as_uint(p1[0]);
                afr[mf][2] = __float_as_uint(p0[4]);
                afr[mf][3] = __float_as_uint(p1[4]);
            }
            #pragma unroll
            for (int nf = 0; nf < 4; ++nf) {
                int n = warp_n*32 + nf*8 + gid;
                bfr[nf][0] = __float_as_uint(bsp[(kk + tig    )*BS_NS + n]);
                bfr[nf][1] = __float_as_uint(bsp[(kk + tig + 4)*BS_NS + n]);
            }
            #pragma unroll
            for (int mf = 0; mf < 4; ++mf) {
                #pragma unroll
                for (int nf = 0; nf < 4; ++nf) {
                    asm volatile(
                        "mma.sync.aligned.m16n8k8.row.col.f32.tf32.tf32.f32 "
                        "{%0,%1,%2,%3}, {%4,%5,%6,%7}, {%8,%9}, {%0,%1,%2,%3};\n"
                        : "+f"(acc[mf][nf][0]), "+f"(acc[mf][nf][1]),
                          "+f"(acc[mf][nf][2]), "+f"(acc[mf][nf][3])
                        : "r"(afr[mf][0]), "r"(afr[mf][1]),
                          "r"(afr[mf][2]), "r"(afr[mf][3]),
                          "r"(bfr[nf][0]), "r"(bfr[nf][1]));
                }
            }
        }
    }

    // Epilogue: scale by demod, write NHWC output (32B-sector coalesced)
    #pragma unroll
    for (int mf = 0; mf < 4; ++mf) {
        int i0 = warp_m*64 + mf*16 + gid;
        int hi = i0 >> 3, wi = i0 & 7;
        size_t r0 = ((size_t)((b*HDIM + h0 + hi)*WDIM + (w0 + wi))) * COUT;
        size_t r1 = r0 + (size_t)WDIM * COUT;     // i0+8 -> next image row, same column
        #pragma unroll
        for (int nf = 0; nf < 4; ++nf) {
            int col = co0 + warp_n*32 + nf*8 + 2*tig;
            float2 d = *reinterpret_cast<const float2*>(g_demod + b*COUT + col);
            float2 v;
            v.x = acc[mf][nf][0] * d.x;
            v.y = acc[mf][nf][1] * d.y;
            *reinterpret_cast<float2*>(out + r0 + col) = v;
            v.x = acc[mf][nf][2] * d.x;
            v.y = acc[mf][nf][3] * d.y;
            *reinterpret_cast<float2*>(out + r1 + col) = v;
        }
    }
}

// ---------------- launch ----------------

extern "C" void kernel_launch(void* const* d_in, const int* in_sizes, int n_in,
                              void* d_out, int out_size) {
    (void)in_sizes; (void)n_in; (void)out_size;
    const float* x     = (const float*)d_in[0];   // [16,64,64,256] f32
    const float* style = (const float*)d_in[1];   // [16,256] f32
    const float* kern  = (const float*)d_in[2];   // [3,3,256,256] f32
    float* out = (float*)d_out;                   // [16,64,64,256] f32

    prep_w_kernel<<<(NTAP*CIN*COUT/4)/256, 256>>>(kern);            // 576 blocks
    prep_demod_kernel<<<BQ, COUT>>>(kern, style);                    // 16 blocks
    prep_x_kernel<<<((size_t)BQ*HDIM*WDIM*CIN/4)/256, 256>>>(x, style);  // 16384 blocks
    modconv_kernel<<<(BQ*HDIM*WDIM/(TH*TW)) * (COUT/128), 256>>>(out);   // 1024 blocks
}

// round 6
// speedup vs baseline: 1.9158x; 1.9158x over previous
#include <cuda_runtime.h>
#include <cstdint>
#include <cstddef>

#define BQ   16
#define HDIM 64
#define WDIM 64
#define CIN  256
#define COUT 256
#define NTAP 9

#define TH 16
#define TW 8
#define BK 32
#define NCHUNK (CIN/BK)            /* 8 */
#define NS (NTAP*NCHUNK)           /* 72 stages */
#define XS_PS 36                   /* floats per halo pixel: 32 ci + 4 pad */
#define BS_NS 136                  /* floats per B k-row: 128 + 8 pad */
#define HP (TH+2)
#define WP (TW+2)
#define NPIX (HP*WP)               /* 180 halo pixels */

/* dynamic smem layout (bytes) */
#define SM_DEMOD 0                          /* 256 f */
#define SM_XS0   1024
#define XS_BYTES (NPIX*XS_PS*4)             /* 25920 */
#define SM_XS1   (SM_XS0 + XS_BYTES)        /* 26944 */
#define SM_BS    (SM_XS1 + XS_BYTES)        /* 52864 */
#define BS_BYTES (BK*BS_NS*4)               /* 17408 */
#define SM_TOTAL (SM_BS + 3*BS_BYTES)       /* 105088 */

// Scratch (device globals; no runtime allocation)
__device__ float g_xmod[(size_t)BQ*HDIM*WDIM*CIN];   // modulated + tf32-rounded x
__device__ float g_wt[NTAP*CIN*COUT];                // tf32-rounded weights [tap][ci][co]
__device__ float g_dpart[BQ*NTAP*COUT];
__device__ float g_demod[BQ*COUT];

__device__ __forceinline__ float rna_tf32(float f) {
    uint32_t u;
    asm("cvt.rna.tf32.f32 %0, %1;" : "=r"(u) : "f"(f));
    return __uint_as_float(u);
}

// ---------------- prep kernels ----------------

__global__ void prep_w_kernel(const float* __restrict__ kern) {
    int i = blockIdx.x * blockDim.x + threadIdx.x;          // float4 index, exact grid
    float4 v = reinterpret_cast<const float4*>(kern)[i];
    v.x = rna_tf32(v.x); v.y = rna_tf32(v.y);
    v.z = rna_tf32(v.z); v.w = rna_tf32(v.w);
    reinterpret_cast<float4*>(g_wt)[i] = v;
}

__global__ void prep_demod_part(const float* __restrict__ kern,
                                const float* __restrict__ style) {
    int tap = blockIdx.x;     // 9
    int b   = blockIdx.y;     // 16
    int co  = threadIdx.x;    // 256
    float acc = 0.0f;
    #pragma unroll 4
    for (int ci = 0; ci < CIN; ++ci) {
        float s = style[b*CIN + ci] + 1.0f;
        float v = kern[((size_t)(tap*CIN + ci))*COUT + co];
        acc += v*v*s*s;
    }
    g_dpart[(b*NTAP + tap)*COUT + co] = acc;
}

__global__ void prep_demod_fin() {
    int b = blockIdx.x, co = threadIdx.x;
    float a = 0.0f;
    #pragma unroll
    for (int t = 0; t < NTAP; ++t) a += g_dpart[(b*NTAP + t)*COUT + co];
    g_demod[b*COUT + co] = rsqrtf(a + 1e-8f);
}

__global__ void prep_x_kernel(const float* __restrict__ x,
                              const float* __restrict__ style) {
    int i = blockIdx.x * blockDim.x + threadIdx.x;          // float4 index, exact grid
    int e = i << 2;
    int ci = e & (CIN - 1);
    int b  = e >> 20;                                       // 2^20 elems per sample
    float4 v = reinterpret_cast<const float4*>(x)[i];
    float4 s = reinterpret_cast<const float4*>(style)[(b*CIN + ci) >> 2];
    v.x = rna_tf32(v.x * (s.x + 1.0f));
    v.y = rna_tf32(v.y * (s.y + 1.0f));
    v.z = rna_tf32(v.z * (s.z + 1.0f));
    v.w = rna_tf32(v.w * (s.w + 1.0f));
    reinterpret_cast<float4*>(g_xmod)[i] = v;
}

// ---------------- main implicit-GEMM conv (mma.sync tf32) ----------------

__global__ void __launch_bounds__(256, 2) modconv_kernel(float* __restrict__ out) {
    extern __shared__ char smem[];
    float* sdemod = reinterpret_cast<float*>(smem + SM_DEMOD);

    const int tid  = threadIdx.x;
    const int lane = tid & 31;
    const int wid  = tid >> 5;
    const int warp_m = wid >> 2;   // 0..1
    const int warp_n = wid & 3;    // 0..3
    const int gid = lane >> 2;
    const int tig = lane & 3;

    const int bt     = blockIdx.x;
    const int n_tile = bt & 1;
    const int mt     = bt >> 1;
    const int b      = mt >> 5;
    const int tI     = mt & 31;
    const int h0     = (tI >> 3) << 4;     // *16
    const int w0     = (tI & 7) << 3;      // *8
    const int co0    = n_tile << 7;        // *128

    // A-fragment pixel offsets (floats, already *XS_PS), halo origin (+1,+1)
    int pixo[8];
    #pragma unroll
    for (int mf = 0; mf < 4; ++mf) {
        #pragma unroll
        for (int hf = 0; hf < 2; ++hf) {
            int i  = warp_m*64 + mf*16 + hf*8 + gid;
            int hi = i >> 3, wi = i & 7;
            pixo[mf*2 + hf] = ((hi + 1)*WP + (wi + 1)) * XS_PS;
        }
    }

    const uint32_t sbase = (uint32_t)__cvta_generic_to_shared(smem);

    // load demod row
    sdemod[tid] = g_demod[b*COUT + tid];

    auto stage_x = [&](int chunk) {
        const uint32_t xb = sbase + ((chunk & 1) ? SM_XS1 : SM_XS0);
        const int ci0 = chunk * BK;
        #pragma unroll 1
        for (int t = tid; t < NPIX * (BK/4); t += 256) {      // 1440 float4 tasks
            int pix = t >> 3;
            int c4  = t & 7;
            int hh  = pix / WP;
            int ww  = pix - hh * WP;
            int gh  = h0 - 1 + hh;
            int gw  = w0 - 1 + ww;
            bool ok = ((unsigned)gh < HDIM) && ((unsigned)gw < WDIM);
            const float* src = g_xmod;
            if (ok) src = g_xmod + ((size_t)((b*HDIM + gh)*WDIM + gw))*CIN + ci0 + c4*4;
            int sz = ok ? 16 : 0;
            uint32_t dst = xb + (uint32_t)(pix*XS_PS + c4*4) * 4u;
            asm volatile("cp.async.cg.shared.global [%0], [%1], 16, %2;\n"
                         :: "r"(dst), "l"(src), "r"(sz));
        }
    };

    auto stage_b = [&](int f) {
        int tap   = f % NTAP;
        int chunk = f / NTAP;
        int krow  = tap*CIN + chunk*BK;
        uint32_t base = sbase + SM_BS + (f % 3)*BS_BYTES;
        #pragma unroll 1
        for (int t = tid; t < BK * 32; t += 256) {            // 1024 float4 tasks
            int kr = t >> 5;
            int n4 = t & 31;
            const float* src = g_wt + (size_t)(krow + kr)*COUT + co0 + n4*4;
            uint32_t dst = base + (uint32_t)(kr*BS_NS + n4*4) * 4u;
            asm volatile("cp.async.cg.shared.global [%0], [%1], 16;\n"
                         :: "r"(dst), "l"(src));
        }
    };

    auto fill = [&](int f) {
        if ((f % NTAP) == 0) stage_x(f / NTAP);
        stage_b(f);
        asm volatile("cp.async.commit_group;\n");
    };

    float acc[4][4][4];
    #pragma unroll
    for (int mf = 0; mf < 4; ++mf)
        #pragma unroll
        for (int nf = 0; nf < 4; ++nf)
            #pragma unroll
            for (int r = 0; r < 4; ++r) acc[mf][nf][r] = 0.0f;

    // Prologue: stages 0 and 1 in flight
    fill(0);
    fill(1);

    #pragma unroll 1
    for (int s = 0; s < NS; ++s) {
        // group for stage s complete (own copies); allow stage s+1's group in flight
        if (s + 2 < NS) asm volatile("cp.async.wait_group 1;\n");
        else            asm volatile("cp.async.wait_group 0;\n");
        // one barrier: (a) stage-s data visible to all warps,
        // (b) all warps done with stage s-1 MMAs -> B buf (s+2)%3 and xs buf reusable
        __syncthreads();

        if (s + 2 < NS) fill(s + 2);

        const int tap   = s % NTAP;
        const int chunk = s / NTAP;
        const float* xsp = reinterpret_cast<const float*>(
            smem + ((chunk & 1) ? SM_XS1 : SM_XS0));
        const float* bsp = reinterpret_cast<const float*>(
            smem + SM_BS + (s % 3)*BS_BYTES);
        const int toff = ((tap/3)*WP + (tap%3) - (WP + 1)) * XS_PS;

        #pragma unroll
        for (int kk = 0; kk < BK; kk += 8) {
            uint32_t afr[4][4], bfr[4][2];
            #pragma unroll
            for (int mf = 0; mf < 4; ++mf) {
                const float* p0 = xsp + pixo[mf*2 + 0] + toff + kk + tig;
                const float* p1 = xsp + pixo[mf*2 + 1] + toff + kk + tig;
                afr[mf][0] = __float_as_uint(p0[0]);
                afr[mf][1] = __float_as_uint(p1[0]);
                afr[mf][2] = __float_as_uint(p0[4]);
                afr[mf][3] = __float_as_uint(p1[4]);
            }
            #pragma unroll
            for (int nf = 0; nf < 4; ++nf) {
                int n = warp_n*32 + nf*8 + gid;
                bfr[nf][0] = __float_as_uint(bsp[(kk + tig    )*BS_NS + n]);
                bfr[nf][1] = __float_as_uint(bsp[(kk + tig + 4)*BS_NS + n]);
            }
            #pragma unroll
            for (int mf = 0; mf < 4; ++mf) {
                #pragma unroll
                for (int nf = 0; nf < 4; ++nf) {
                    asm volatile(
                        "mma.sync.aligned.m16n8k8.row.col.f32.tf32.tf32.f32 "
                        "{%0,%1,%2,%3}, {%4,%5,%6,%7}, {%8,%9}, {%0,%1,%2,%3};\n"
                        : "+f"(acc[mf][nf][0]), "+f"(acc[mf][nf][1]),
                          "+f"(acc[mf][nf][2]), "+f"(acc[mf][nf][3])
                        : "r"(afr[mf][0]), "r"(afr[mf][1]),
                          "r"(afr[mf][2]), "r"(afr[mf][3]),
                          "r"(bfr[nf][0]), "r"(bfr[nf][1]));
                }
            }
        }
    }

    // Epilogue: scale by demod (from smem), coalesced float2 stores
    #pragma unroll
    for (int mf = 0; mf < 4; ++mf) {
        int i0 = warp_m*64 + mf*16 + gid;
        int hi = i0 >> 3, wi = i0 & 7;
        size_t r0 = ((size_t)((b*HDIM + h0 + hi)*WDIM + (w0 + wi))) * COUT;
        size_t r1 = r0 + (size_t)WDIM * COUT;     // pixel i0+8 -> next image row
        #pragma unroll
        for (int nf = 0; nf < 4; ++nf) {
            int col = co0 + warp_n*32 + nf*8 + 2*tig;
            float dx = sdemod[col], dy = sdemod[col + 1];
            float2 v;
            v.x = acc[mf][nf][0] * dx;
            v.y = acc[mf][nf][1] * dy;
            *reinterpret_cast<float2*>(out + r0 + col) = v;
            v.x = acc[mf][nf][2] * dx;
            v.y = acc[mf][nf][3] * dy;
            *reinterpret_cast<float2*>(out + r1 + col) = v;
        }
    }
}

// ---------------- launch ----------------

extern "C" void kernel_launch(void* const* d_in, const int* in_sizes, int n_in,
                              void* d_out, int out_size) {
    (void)in_sizes; (void)n_in; (void)out_size;
    const float* x     = (const float*)d_in[0];   // [16,64,64,256] f32
    const float* style = (const float*)d_in[1];   // [16,256] f32
    const float* kern  = (const float*)d_in[2];   // [3,3,256,256] f32
    float* out = (float*)d_out;                   // [16,64,64,256] f32

    cudaFuncSetAttribute(modconv_kernel,
                         cudaFuncAttributeMaxDynamicSharedMemorySize, SM_TOTAL);

    prep_w_kernel<<<(NTAP*CIN*COUT/4)/256, 256>>>(kern);                 // 576 blocks
    prep_demod_part<<<dim3(NTAP, BQ), COUT>>>(kern, style);              // 144 blocks
    prep_demod_fin<<<BQ, COUT>>>();
    prep_x_kernel<<<(int)(((size_t)BQ*HDIM*WDIM*CIN/4)/256), 256>>>(x, style);
    modconv_kernel<<<(BQ*HDIM*WDIM/(TH*TW)) * (COUT/128), 256, SM_TOTAL>>>(out);
}